// round 2
// baseline (speedup 1.0000x reference)
#include <cuda_runtime.h>

#define B_  2
#define N_  2048
#define D_  1024
#define H_  16
#define DH_ 64
#define M_  (B_ * N_)          // 4096 total rows
#define ATT_SCALE 0.03125f     // 1024^-0.5

// ---------------- scratch (no allocations allowed) ----------------
__device__ float g_Q [M_ * D_];    // 16 MB  (b*n, h*dh)
__device__ float g_K [M_ * DH_];   // 1 MB
__device__ float g_V [M_ * DH_];   // 1 MB
__device__ float g_AO[M_ * D_];    // 16 MB  attention output (b, n, h*dh)

// ============================================================================
// SGEMM: C[M,N] = A[M,K] * B[N,K]^T (+ bias[N])
// 128x128 tile, BK=16, 256 threads, 8x8 per thread.
// M must be a multiple of 128, K a multiple of 16. N is guarded.
// ============================================================================
__global__ __launch_bounds__(256) void sgemm_abt(
    const float* __restrict__ A, const float* __restrict__ Bm,
    const float* __restrict__ bias, float* __restrict__ C,
    int M, int N, int K)
{
    __shared__ float As[16][128];
    __shared__ float Bs[16][128];

    const int tid = threadIdx.x;
    const int ty  = tid >> 4;        // 0..15 -> rows ty*8..+7
    const int tx  = tid & 15;        // 0..15 -> cols tx*8..+7
    const int m0  = blockIdx.y * 128;
    const int n0  = blockIdx.x * 128;

    float acc[8][8];
#pragma unroll
    for (int i = 0; i < 8; i++)
#pragma unroll
        for (int j = 0; j < 8; j++) acc[i][j] = 0.f;

    for (int kt = 0; kt < K; kt += 16) {
        // cooperative load: 128 rows x 16 k each for A and B (transposed in smem)
#pragma unroll
        for (int l = 0; l < 2; l++) {
            int f   = tid + l * 256;     // float4 index 0..511
            int row = f >> 2;            // 0..127
            int ks  = f & 3;             // 0..3 -> k = ks*4..+3
            float4 av = *(const float4*)&A[(size_t)(m0 + row) * K + kt + ks * 4];
            As[ks * 4 + 0][row] = av.x;
            As[ks * 4 + 1][row] = av.y;
            As[ks * 4 + 2][row] = av.z;
            As[ks * 4 + 3][row] = av.w;
            float4 bv = make_float4(0.f, 0.f, 0.f, 0.f);
            if (n0 + row < N)
                bv = *(const float4*)&Bm[(size_t)(n0 + row) * K + kt + ks * 4];
            Bs[ks * 4 + 0][row] = bv.x;
            Bs[ks * 4 + 1][row] = bv.y;
            Bs[ks * 4 + 2][row] = bv.z;
            Bs[ks * 4 + 3][row] = bv.w;
        }
        __syncthreads();

#pragma unroll
        for (int k = 0; k < 16; k++) {
            float4 a0 = *(const float4*)&As[k][ty * 8];
            float4 a1 = *(const float4*)&As[k][ty * 8 + 4];
            float4 b0 = *(const float4*)&Bs[k][tx * 8];
            float4 b1 = *(const float4*)&Bs[k][tx * 8 + 4];
            float ar[8] = {a0.x, a0.y, a0.z, a0.w, a1.x, a1.y, a1.z, a1.w};
            float br[8] = {b0.x, b0.y, b0.z, b0.w, b1.x, b1.y, b1.z, b1.w};
#pragma unroll
            for (int i = 0; i < 8; i++)
#pragma unroll
                for (int j = 0; j < 8; j++)
                    acc[i][j] = fmaf(ar[i], br[j], acc[i][j]);
        }
        __syncthreads();
    }

#pragma unroll
    for (int i = 0; i < 8; i++) {
        int gr = m0 + ty * 8 + i;
#pragma unroll
        for (int j = 0; j < 8; j++) {
            int gc = n0 + tx * 8 + j;
            if (gc < N) {
                float v = acc[i][j];
                if (bias) v += bias[gc];
                C[(size_t)gr * N + gc] = v;
            }
        }
    }
}

// ============================================================================
// Flash attention (fp32, online softmax). One CTA = 64 query rows of one
// (batch, head). 256 threads as 16x16; each thread: 4 rows x 4 cols.
// Shared K/V head (MQA). Causal + query mask. Writes AO in (b, n, h*dh).
// ============================================================================
__device__ __forceinline__ float redmax16(float v) {
    v = fmaxf(v, __shfl_xor_sync(0xffffffffu, v, 1));
    v = fmaxf(v, __shfl_xor_sync(0xffffffffu, v, 2));
    v = fmaxf(v, __shfl_xor_sync(0xffffffffu, v, 4));
    v = fmaxf(v, __shfl_xor_sync(0xffffffffu, v, 8));
    return v;
}
__device__ __forceinline__ float redsum16(float v) {
    v += __shfl_xor_sync(0xffffffffu, v, 1);
    v += __shfl_xor_sync(0xffffffffu, v, 2);
    v += __shfl_xor_sync(0xffffffffu, v, 4);
    v += __shfl_xor_sync(0xffffffffu, v, 8);
    return v;
}

__global__ __launch_bounds__(256) void flash_kernel(
    const float* __restrict__ Q, const float* __restrict__ Kg,
    const float* __restrict__ Vg, const int* __restrict__ mask,
    float* __restrict__ AO)
{
    extern __shared__ float sm[];
    float* Qs = sm;             // [64][64]
    float* Ks = sm + 4096;      // [64][64] xor-swizzled by d-chunk
    float* Vs = sm + 8192;      // [64][64]
    float* Ps = sm + 12288;     // [64][64]

    const int tx  = threadIdx.x;        // 0..15
    const int ty  = threadIdx.y;        // 0..15
    const int tid = ty * 16 + tx;
    const int m0  = blockIdx.x * 64;    // query tile start (within batch)
    const int h   = blockIdx.y;
    const int b   = blockIdx.z;

    // load Q tile (64 x 64) for this head
    const size_t qbase = ((size_t)(b * N_ + m0)) * D_ + h * DH_;
#pragma unroll
    for (int l = 0; l < 4; l++) {
        int f = tid + l * 256;          // 0..1023 float4s
        int r = f >> 4, cs = f & 15;
        *(float4*)&Qs[r * 64 + cs * 4] =
            *(const float4*)&Q[qbase + (size_t)r * D_ + cs * 4];
    }

    int qm[4];
#pragma unroll
    for (int a = 0; a < 4; a++)
        qm[a] = mask[b * N_ + m0 + 4 * ty + a];   // bool serialized as int32

    float o[4][4];
    float mr[4], lr[4];
#pragma unroll
    for (int a = 0; a < 4; a++) {
        mr[a] = -3.402823466e38f;
        lr[a] = 0.f;
#pragma unroll
        for (int c = 0; c < 4; c++) o[a][c] = 0.f;
    }

    const int nkt = (m0 >> 6) + 1;      // causal: key tiles 0..m0/64
    for (int kt = 0; kt < nkt; kt++) {
        __syncthreads();   // previous iteration's reads of Ks/Vs are done
        const size_t kvbase = ((size_t)(b * N_ + kt * 64)) * DH_;
#pragma unroll
        for (int l = 0; l < 4; l++) {
            int f = tid + l * 256;
            int r = f >> 4, cs = f & 15;
            float4 kv = *(const float4*)&Kg[kvbase + r * 64 + cs * 4];
            *(float4*)&Ks[r * 64 + 4 * (cs ^ (r & 15))] = kv;   // swizzle
            float4 vv = *(const float4*)&Vg[kvbase + r * 64 + cs * 4];
            *(float4*)&Vs[r * 64 + cs * 4] = vv;
        }
        __syncthreads();

        // S = Q K^T  (rows 4ty+a, cols 4tx+c)
        float s[4][4];
#pragma unroll
        for (int a = 0; a < 4; a++)
#pragma unroll
            for (int c = 0; c < 4; c++) s[a][c] = 0.f;

#pragma unroll 4
        for (int dc = 0; dc < 16; dc++) {
            float qa[4][4], kc[4][4];
#pragma unroll
            for (int a = 0; a < 4; a++) {
                float4 t = *(const float4*)&Qs[(4 * ty + a) * 64 + dc * 4];
                qa[a][0] = t.x; qa[a][1] = t.y; qa[a][2] = t.z; qa[a][3] = t.w;
            }
#pragma unroll
            for (int c = 0; c < 4; c++) {
                int col = 4 * tx + c;
                float4 t = *(const float4*)&Ks[col * 64 + 4 * (dc ^ (col & 15))];
                kc[c][0] = t.x; kc[c][1] = t.y; kc[c][2] = t.z; kc[c][3] = t.w;
            }
#pragma unroll
            for (int a = 0; a < 4; a++)
#pragma unroll
                for (int c = 0; c < 4; c++) {
                    s[a][c] = fmaf(qa[a][0], kc[c][0], s[a][c]);
                    s[a][c] = fmaf(qa[a][1], kc[c][1], s[a][c]);
                    s[a][c] = fmaf(qa[a][2], kc[c][2], s[a][c]);
                    s[a][c] = fmaf(qa[a][3], kc[c][3], s[a][c]);
                }
        }

        // scale + causal/query mask
#pragma unroll
        for (int a = 0; a < 4; a++) {
            int gi = m0 + 4 * ty + a;
#pragma unroll
            for (int c = 0; c < 4; c++) {
                int gj = kt * 64 + 4 * tx + c;
                s[a][c] = (qm[a] && gj <= gi) ? s[a][c] * ATT_SCALE : -1e30f;
            }
        }

        // online softmax update
#pragma unroll
        for (int a = 0; a < 4; a++) {
            float tm = fmaxf(fmaxf(s[a][0], s[a][1]), fmaxf(s[a][2], s[a][3]));
            tm = redmax16(tm);
            float nm  = fmaxf(mr[a], tm);
            float fac = __expf(mr[a] - nm);
            mr[a] = nm;
            float p0 = __expf(s[a][0] - nm);
            float p1 = __expf(s[a][1] - nm);
            float p2 = __expf(s[a][2] - nm);
            float p3 = __expf(s[a][3] - nm);
            *(float4*)&Ps[(4 * ty + a) * 64 + 4 * tx] = make_float4(p0, p1, p2, p3);
            float rs = redsum16(p0 + p1 + p2 + p3);
            lr[a] = lr[a] * fac + rs;
#pragma unroll
            for (int c = 0; c < 4; c++) o[a][c] *= fac;
        }
        __syncwarp();   // Ps producer group == consumer group (same ty rows)

        // O += P @ V
        for (int k4 = 0; k4 < 64; k4 += 4) {
            float pr[4][4], vr[4][4];
#pragma unroll
            for (int a = 0; a < 4; a++) {
                float4 t = *(const float4*)&Ps[(4 * ty + a) * 64 + k4];
                pr[a][0] = t.x; pr[a][1] = t.y; pr[a][2] = t.z; pr[a][3] = t.w;
            }
#pragma unroll
            for (int kk = 0; kk < 4; kk++) {
                float4 t = *(const float4*)&Vs[(k4 + kk) * 64 + 4 * tx];
                vr[kk][0] = t.x; vr[kk][1] = t.y; vr[kk][2] = t.z; vr[kk][3] = t.w;
            }
#pragma unroll
            for (int a = 0; a < 4; a++)
#pragma unroll
                for (int c = 0; c < 4; c++) {
                    o[a][c] = fmaf(pr[a][0], vr[0][c], o[a][c]);
                    o[a][c] = fmaf(pr[a][1], vr[1][c], o[a][c]);
                    o[a][c] = fmaf(pr[a][2], vr[2][c], o[a][c]);
                    o[a][c] = fmaf(pr[a][3], vr[3][c], o[a][c]);
                }
        }
    }

    // normalize and write AO (b, n, h*dh)
#pragma unroll
    for (int a = 0; a < 4; a++) {
        float inv = 1.f / lr[a];
        size_t obase = ((size_t)(b * N_ + m0 + 4 * ty + a)) * D_ + h * DH_ + 4 * tx;
        *(float4*)&AO[obase] = make_float4(o[a][0] * inv, o[a][1] * inv,
                                           o[a][2] * inv, o[a][3] * inv);
    }
}

// ============================================================================
extern "C" void kernel_launch(void* const* d_in, const int* in_sizes, int n_in,
                              void* d_out, int out_size)
{
    const float* x    = (const float*)d_in[0];
    const int*   mask = (const int*)d_in[1];     // bool serialized as int32
    const float* Wq   = (const float*)d_in[2];
    const float* Wk   = (const float*)d_in[3];
    const float* Wv   = (const float*)d_in[4];
    const float* Wfc  = (const float*)d_in[5];
    const float* bfc  = (const float*)d_in[6];
    float*       out  = (float*)d_out;

    float *Qb, *Kb, *Vb, *AOb;
    cudaGetSymbolAddress((void**)&Qb,  g_Q);
    cudaGetSymbolAddress((void**)&Kb,  g_K);
    cudaGetSymbolAddress((void**)&Vb,  g_V);
    cudaGetSymbolAddress((void**)&AOb, g_AO);

    const int FLASH_SMEM = 4 * 4096 * 4;   // 64 KB
    cudaFuncSetAttribute(flash_kernel,
                         cudaFuncAttributeMaxDynamicSharedMemorySize, FLASH_SMEM);

    // Q = X Wq^T  (4096 x 1024)
    sgemm_abt<<<dim3(D_ / 128, M_ / 128), 256>>>(x, Wq, nullptr, Qb, M_, D_, D_);
    // K = X Wk^T, V = X Wv^T  (4096 x 64)
    sgemm_abt<<<dim3(1, M_ / 128), 256>>>(x, Wk, nullptr, Kb, M_, DH_, D_);
    sgemm_abt<<<dim3(1, M_ / 128), 256>>>(x, Wv, nullptr, Vb, M_, DH_, D_);
    // flash attention -> AO (b, n, h*dh)
    flash_kernel<<<dim3(N_ / 64, H_, B_), dim3(16, 16), FLASH_SMEM>>>(
        Qb, Kb, Vb, mask, AOb);
    // out = AO Wfc^T + bfc
    sgemm_abt<<<dim3(D_ / 128, M_ / 128), 256>>>(AOb, Wfc, bfc, out, M_, D_, D_);
}